// round 10
// baseline (speedup 1.0000x reference)
#include <cuda_runtime.h>
#include <cuda_fp16.h>
#include <math.h>
#include <stdint.h>

// Problem constants
#define BATCH   4096
#define INDIM   512
#define LATENT  512
#define NHEAD   8
#define DHEAD   64
#define KVBN    1032            // H*(2D+1) = 8*129
#define LN_EPS  1e-5f

// ---------------- scratch (device globals; no runtime alloc allowed) ----------------
__device__ __half g_xh   [BATCH * INDIM];
__device__ __half g_ipwh [INDIM * LATENT];
__device__ __half g_mgwh [1024 * LATENT];
__device__ __half g_kvbwh[LATENT * KVBN];
__device__ __half g_hcath[BATCH * 1024];     // [LN(h) | z] fp16 (GEMM1 writes cols 0..511)
__device__ __half g_h2h  [BATCH * LATENT];   // GEMM2 out fp16
__device__ float  g_kvb  [BATCH * KVBN];     // GEMM3 out fp32

__device__ __forceinline__ uint32_t smem_u32(const void* p) {
    return (uint32_t)__cvta_generic_to_shared(p);
}
__device__ __forceinline__ void cp_async16(uint32_t dst, const void* src) {
    asm volatile("cp.async.cg.shared.global [%0], [%1], 16;\n" :: "r"(dst), "l"(src));
}
__device__ __forceinline__ void cp_commit() { asm volatile("cp.async.commit_group;\n"); }
__device__ __forceinline__ void cp_wait1()  { asm volatile("cp.async.wait_group 1;\n"); }

__device__ __forceinline__ void ldsm_x4(uint32_t& r0, uint32_t& r1, uint32_t& r2, uint32_t& r3, uint32_t addr) {
    asm volatile("ldmatrix.sync.aligned.m8n8.x4.shared.b16 {%0,%1,%2,%3}, [%4];"
                 : "=r"(r0), "=r"(r1), "=r"(r2), "=r"(r3) : "r"(addr));
}
__device__ __forceinline__ void ldsm_x4_t(uint32_t& r0, uint32_t& r1, uint32_t& r2, uint32_t& r3, uint32_t addr) {
    asm volatile("ldmatrix.sync.aligned.m8n8.x4.trans.shared.b16 {%0,%1,%2,%3}, [%4];"
                 : "=r"(r0), "=r"(r1), "=r"(r2), "=r"(r3) : "r"(addr));
}

// ---------------- fused pre-pass: f32->f16 for x + 3 weights, plus strided z -> hcat[:,512:] -------
__global__ __launch_bounds__(256) void cvt_pre_kernel(
    const float2* __restrict__ x,
    const float2* __restrict__ ipw,
    const float2* __restrict__ mgw,
    const float2* __restrict__ kvbw,
    const float2* __restrict__ z)
{
    const int t = blockIdx.x * 256 + threadIdx.x;
    const int stride = gridDim.x * 256;
    __half2* xh   = (__half2*)g_xh;
    __half2* ipwh = (__half2*)g_ipwh;
    __half2* mgwh = (__half2*)g_mgwh;
    __half2* kvbwh= (__half2*)g_kvbwh;
    __half2* hc   = (__half2*)g_hcath;
    for (int i = t; i < BATCH * INDIM / 2; i += stride)  xh[i]   = __float22half2_rn(x[i]);
    for (int i = t; i < INDIM * LATENT / 2; i += stride) ipwh[i] = __float22half2_rn(ipw[i]);
    for (int i = t; i < 1024 * LATENT / 2; i += stride)  mgwh[i] = __float22half2_rn(mgw[i]);
    for (int i = t; i < LATENT * KVBN / 2; i += stride)  kvbwh[i]= __float22half2_rn(kvbw[i]);
    // z (B x 512 f32) -> hcat[:, 512:1024] fp16 (row stride 512 half2)
    for (int i = t; i < BATCH * 256; i += stride) {
        int b = i >> 8, c = i & 255;
        hc[(size_t)b * 512 + 256 + c] = __float22half2_rn(z[i]);
    }
}

// ---------------- fp16 tensor-core GEMM: C = A(MxK) * B(KxN) + bias ----------------
// BM=64, BN=64, BK=32, 128 threads (4 warps, 2x2), warp tile 32x32.
// m16n8k16 f16 mma, f32 accumulate. 3-stage cp.async ring, ldmatrix fragment loads.
#define HGBM 64
#define HGBN 64
#define HGBK 32
#define SAH  40
#define SBH  72
#define NST  3

template<bool NB, typename OutT>
__global__ __launch_bounds__(128, 4) void h_gemm(
    int M, int N, int K,
    const __half* __restrict__ A, int lda,
    const __half* __restrict__ B, int ldb,
    const float* __restrict__ bias,
    OutT* __restrict__ C, int ldc)
{
    __shared__ __half As[NST][HGBM][SAH];
    __shared__ __half Bs[NST][HGBK][SBH];

    const int tid  = threadIdx.x;
    const int wid  = tid >> 5;
    const int lane = tid & 31;
    const int grp  = lane >> 2;
    const int tig  = lane & 3;
    const int warp_m = (wid & 1) * 32;
    const int warp_n = (wid >> 1) * 32;
    const int block_row = blockIdx.y * HGBM;
    const int block_col = blockIdx.x * HGBN;

    float acc[2][4][4];
    #pragma unroll
    for (int a = 0; a < 2; a++)
        #pragma unroll
        for (int b = 0; b < 4; b++)
            #pragma unroll
            for (int c = 0; c < 4; c++) acc[a][b][c] = 0.f;

    const int KT = K / HGBK;

    auto load_stage = [&](int s, int kt) {
        const int k0 = kt * HGBK;
        // A: 64 rows x 4 chunks(16B) = 256 chunks -> 2/thread
        #pragma unroll
        for (int i = 0; i < 2; i++) {
            int idx = tid + 128 * i;
            int r = idx >> 2;
            int j = (idx & 3) * 8;
            cp_async16(smem_u32(&As[s][r][j]),
                       A + (size_t)(block_row + r) * lda + k0 + j);
        }
        // B: 32 k-rows x 8 chunks = 256 chunks -> 2/thread
        #pragma unroll
        for (int i = 0; i < 2; i++) {
            int idx = tid + 128 * i;
            int kk = idx >> 3;
            int c8 = (idx & 7) * 8;
            if (!NB || (block_col + c8) < N) {
                cp_async16(smem_u32(&Bs[s][kk][c8]),
                           B + (size_t)(k0 + kk) * ldb + block_col + c8);
            }
        }
    };

    load_stage(0, 0); cp_commit();
    load_stage(1, 1); cp_commit();

    const int a_row = warp_m + (lane & 15);
    const int a_k8  = (lane >> 4) << 3;
    const int b_r16 = (lane & 15);
    const int b_n8  = (lane >> 4) << 3;

    for (int kt = 0; kt < KT; kt++) {
        cp_wait1();
        __syncthreads();
        if (kt + 2 < KT) load_stage((kt + 2) % NST, kt + 2);
        cp_commit();

        const int s = kt % NST;
        #pragma unroll
        for (int ks = 0; ks < 2; ks++) {
            const int k0 = ks * 16;
            uint32_t a[2][4];
            #pragma unroll
            for (int mt = 0; mt < 2; mt++) {
                uint32_t addr = smem_u32(&As[s][a_row + mt * 16][k0 + a_k8]);
                ldsm_x4(a[mt][0], a[mt][1], a[mt][2], a[mt][3], addr);
            }
            uint32_t b[2][4];
            #pragma unroll
            for (int bt = 0; bt < 2; bt++) {
                uint32_t addr = smem_u32(&Bs[s][k0 + b_r16][warp_n + bt * 16 + b_n8]);
                ldsm_x4_t(b[bt][0], b[bt][1], b[bt][2], b[bt][3], addr);
            }
            #pragma unroll
            for (int mt = 0; mt < 2; mt++)
                #pragma unroll
                for (int nt = 0; nt < 4; nt++) {
                    const int bt = nt >> 1;
                    const int hp = (nt & 1) * 2;
                    asm volatile(
                        "mma.sync.aligned.m16n8k16.row.col.f32.f16.f16.f32 "
                        "{%0,%1,%2,%3}, {%4,%5,%6,%7}, {%8,%9}, {%0,%1,%2,%3};\n"
                        : "+f"(acc[mt][nt][0]), "+f"(acc[mt][nt][1]),
                          "+f"(acc[mt][nt][2]), "+f"(acc[mt][nt][3])
                        : "r"(a[mt][0]), "r"(a[mt][1]), "r"(a[mt][2]), "r"(a[mt][3]),
                          "r"(b[bt][hp]), "r"(b[bt][hp + 1]));
                }
        }
    }

    #pragma unroll
    for (int mt = 0; mt < 2; mt++) {
        int r0 = block_row + warp_m + mt * 16 + grp;
        #pragma unroll
        for (int nt = 0; nt < 4; nt++) {
            int c = block_col + warp_n + nt * 8 + tig * 2;
            if (!NB || c < N) {
                float b0 = bias[c], b1 = bias[c + 1];
                float o00 = acc[mt][nt][0] + b0, o01 = acc[mt][nt][1] + b1;
                float o10 = acc[mt][nt][2] + b0, o11 = acc[mt][nt][3] + b1;
                if (sizeof(OutT) == 4) {
                    *(float2*)((float*)C + (size_t)r0 * ldc + c)       = make_float2(o00, o01);
                    *(float2*)((float*)C + (size_t)(r0 + 8) * ldc + c) = make_float2(o10, o11);
                } else {
                    *(__half2*)((__half*)C + (size_t)r0 * ldc + c)       = __floats2half2_rn(o00, o01);
                    *(__half2*)((__half*)C + (size_t)(r0 + 8) * ldc + c) = __floats2half2_rn(o10, o11);
                }
            }
        }
    }
}

// ---------------- LayerNorm (512) in-place on g_hcath[:, :512] (fp16, f32 math) ----------------
__global__ __launch_bounds__(256) void ln_kernel(
    const float* __restrict__ gamma,
    const float* __restrict__ beta)
{
    const int b = blockIdx.x;
    __half2* row = (__half2*)(g_hcath + (size_t)b * 1024);
    const int tid = threadIdx.x;

    float2 v = __half22float2(row[tid]);

    __shared__ float red[256];
    red[tid] = v.x + v.y;
    __syncthreads();
    #pragma unroll
    for (int s = 128; s > 0; s >>= 1) {
        if (tid < s) red[tid] += red[tid + s];
        __syncthreads();
    }
    const float mu = red[0] * (1.f / 512.f);
    __syncthreads();

    float d0 = v.x - mu, d1 = v.y - mu;
    red[tid] = d0 * d0 + d1 * d1;
    __syncthreads();
    #pragma unroll
    for (int s = 128; s > 0; s >>= 1) {
        if (tid < s) red[tid] += red[tid + s];
        __syncthreads();
    }
    const float var = red[0] * (1.f / 512.f);
    const float inv = rsqrtf(var + LN_EPS);

    float2 g = *(const float2*)(gamma + 2 * tid);
    float2 be = *(const float2*)(beta + 2 * tid);
    row[tid] = __floats2half2_rn(d0 * inv * g.x + be.x, d1 * inv * g.y + be.y);
}

// ---------------- Oja update: one block per (b,h); W streamed once --------
__global__ __launch_bounds__(256) void oja_final_kernel(
    const float* __restrict__ W,
    float* __restrict__ out)
{
    const int bh = blockIdx.x;              // b*H + h
    const int b  = bh >> 3;
    const int h  = bh & 7;

    const float4* __restrict__ W4 = (const float4*)(W   + (size_t)bh * (DHEAD * DHEAD));
    float4* __restrict__       O4 = (float4*)      (out + (size_t)bh * (DHEAD * DHEAD));
    const float* __restrict__ row = g_kvb + (size_t)b * KVBN + h * (2 * DHEAD + 1);

    __shared__ float  s_vs[DHEAD];
    __shared__ float  s_ks[DHEAD];
    __shared__ float  part[16][DHEAD];
    __shared__ float  red[DHEAD];
    __shared__ float  s_lr, s_max, s_sum;

    const int tid = threadIdx.x;
    if (tid < DHEAD) {
        s_ks[tid] = row[tid];
        s_vs[tid] = tanhf(row[DHEAD + tid]);
    }
    if (tid == 0) s_lr = 1.f / (1.f + expf(-row[2 * DHEAD]));
    __syncthreads();

    const int c4 = tid & 15;
    const int dg = tid >> 4;

    float4 wreg[4];
    float p0 = 0.f, p1 = 0.f, p2 = 0.f, p3 = 0.f;
    #pragma unroll
    for (int i = 0; i < 4; i++) {
        int d = dg + 16 * i;
        float4 w = __ldcs(&W4[d * 16 + c4]);
        wreg[i] = w;
        float v = s_vs[d];
        p0 = fmaf(w.x, v, p0);
        p1 = fmaf(w.y, v, p1);
        p2 = fmaf(w.z, v, p2);
        p3 = fmaf(w.w, v, p3);
    }
    part[dg][4 * c4 + 0] = p0;
    part[dg][4 * c4 + 1] = p1;
    part[dg][4 * c4 + 2] = p2;
    part[dg][4 * c4 + 3] = p3;
    __syncthreads();

    if (tid < DHEAD) {
        float rm = 0.f;
        #pragma unroll
        for (int g = 0; g < 16; g++) rm += part[g][tid];
        red[tid] = s_ks[tid] - rm;
    }
    __syncthreads();
    if (tid < 32) {
        float mx = fmaxf(red[tid], red[tid + 32]);
        #pragma unroll
        for (int o = 16; o > 0; o >>= 1) mx = fmaxf(mx, __shfl_xor_sync(0xffffffffu, mx, o));
        if (tid == 0) s_max = mx;
    }
    __syncthreads();
    if (tid < DHEAD) red[tid] = expf(red[tid] - s_max);
    __syncthreads();
    if (tid < 32) {
        float s = red[tid] + red[tid + 32];
        #pragma unroll
        for (int o = 16; o > 0; o >>= 1) s += __shfl_xor_sync(0xffffffffu, s, o);
        if (tid == 0) s_sum = s;
    }
    __syncthreads();
    if (tid < DHEAD) s_ks[tid] = red[tid] * (s_lr / s_sum);
    __syncthreads();

    const float k0 = s_ks[4 * c4 + 0];
    const float k1 = s_ks[4 * c4 + 1];
    const float k2 = s_ks[4 * c4 + 2];
    const float k3 = s_ks[4 * c4 + 3];
    #pragma unroll
    for (int i = 0; i < 4; i++) {
        int d = dg + 16 * i;
        float v = s_vs[d];
        float4 w = wreg[i];
        float4 o;
        o.x = fmaf(v, k0, w.x);
        o.y = fmaf(v, k1, w.y);
        o.z = fmaf(v, k2, w.z);
        o.w = fmaf(v, k3, w.w);
        __stcs(&O4[d * 16 + c4], o);
    }
}

// ---------------- launch: serial, single stream ----------------
extern "C" void kernel_launch(void* const* d_in, const int* in_sizes, int n_in,
                              void* d_out, int out_size)
{
    const float* x     = (const float*)d_in[0];
    const float* z     = (const float*)d_in[1];
    const float* W     = (const float*)d_in[2];
    const float* ip_w  = (const float*)d_in[3];
    const float* ip_b  = (const float*)d_in[4];
    const float* ln_g  = (const float*)d_in[5];
    const float* ln_b  = (const float*)d_in[6];
    const float* mg_w  = (const float*)d_in[7];
    const float* mg_b  = (const float*)d_in[8];
    const float* kvb_w = (const float*)d_in[9];
    const float* kvb_b = (const float*)d_in[10];
    float* out = (float*)d_out;

    void *p_xh, *p_ipwh, *p_mgwh, *p_kvbwh, *p_hcath, *p_h2h, *p_kvb;
    cudaGetSymbolAddress(&p_xh,    g_xh);
    cudaGetSymbolAddress(&p_ipwh,  g_ipwh);
    cudaGetSymbolAddress(&p_mgwh,  g_mgwh);
    cudaGetSymbolAddress(&p_kvbwh, g_kvbwh);
    cudaGetSymbolAddress(&p_hcath, g_hcath);
    cudaGetSymbolAddress(&p_h2h,   g_h2h);
    cudaGetSymbolAddress(&p_kvb,   g_kvb);

    // 0) fused pre-pass: f32->f16 conversions + z into hcat[:, 512:]
    cvt_pre_kernel<<<1184, 256>>>(
        (const float2*)x, (const float2*)ip_w, (const float2*)mg_w,
        (const float2*)kvb_w, (const float2*)z);

    // 1) hcat[:, :512] = xh @ ipwh + ip_b  (fp16 out, ldc=1024)
    {
        dim3 grid(LATENT / HGBN, BATCH / HGBM);   // (8, 64) = 512 blocks
        h_gemm<false, __half><<<grid, 128>>>(BATCH, LATENT, INDIM,
            (const __half*)p_xh, INDIM, (const __half*)p_ipwh, LATENT, ip_b,
            (__half*)p_hcath, 1024);
    }
    // 2) LayerNorm in place on hcat[:, :512]
    ln_kernel<<<BATCH, 256>>>(ln_g, ln_b);
    // 3) h2h = hcat @ mgwh + mg_b  (fp16 out)
    {
        dim3 grid(LATENT / HGBN, BATCH / HGBM);   // 512 blocks
        h_gemm<false, __half><<<grid, 128>>>(BATCH, LATENT, 1024,
            (const __half*)p_hcath, 1024, (const __half*)p_mgwh, LATENT, mg_b,
            (__half*)p_h2h, LATENT);
    }
    // 4) kvb = h2h @ kvbwh + kvb_b  (fp32 out, N=1032 bounds)
    {
        dim3 grid((KVBN + HGBN - 1) / HGBN, BATCH / HGBM);  // (17, 64) = 1088 blocks
        h_gemm<true, float><<<grid, 128>>>(BATCH, KVBN, LATENT,
            (const __half*)p_h2h, LATENT, (const __half*)p_kvbwh, KVBN, kvb_b,
            (float*)p_kvb, KVBN);
    }
    // 5) Oja update fused
    oja_final_kernel<<<BATCH * NHEAD, 256>>>(W, out);
}

// round 12
// speedup vs baseline: 1.3126x; 1.3126x over previous
#include <cuda_runtime.h>
#include <cuda_fp16.h>
#include <math.h>
#include <stdint.h>

// Problem constants
#define BATCH   4096
#define INDIM   512
#define LATENT  512
#define NHEAD   8
#define DHEAD   64
#define KVBN    1032            // H*(2D+1) = 8*129
#define LN_EPS  1e-5f

// ---------------- scratch (device globals; no runtime alloc allowed) ----------------
__device__ __half g_xh   [BATCH * INDIM];
__device__ __half g_ipwh [INDIM * LATENT];
__device__ __half g_mgwh [1024 * LATENT];
__device__ __half g_kvbwh[LATENT * KVBN];
__device__ __half g_hcath[BATCH * 1024];     // [LN(h) | z] fp16; GEMM1 writes cols 0..511
__device__ __half g_h2h  [BATCH * LATENT];   // GEMM2 out fp16
__device__ float  g_kvb  [BATCH * KVBN];     // GEMM3 out fp32

__device__ __forceinline__ uint32_t smem_u32(const void* p) {
    return (uint32_t)__cvta_generic_to_shared(p);
}
__device__ __forceinline__ void cp_async16(uint32_t dst, const void* src) {
    asm volatile("cp.async.cg.shared.global [%0], [%1], 16;\n" :: "r"(dst), "l"(src));
}
__device__ __forceinline__ void cp_commit() { asm volatile("cp.async.commit_group;\n"); }
__device__ __forceinline__ void cp_wait1()  { asm volatile("cp.async.wait_group 1;\n"); }

__device__ __forceinline__ void ldsm_x4(uint32_t& r0, uint32_t& r1, uint32_t& r2, uint32_t& r3, uint32_t addr) {
    asm volatile("ldmatrix.sync.aligned.m8n8.x4.shared.b16 {%0,%1,%2,%3}, [%4];"
                 : "=r"(r0), "=r"(r1), "=r"(r2), "=r"(r3) : "r"(addr));
}
__device__ __forceinline__ void ldsm_x4_t(uint32_t& r0, uint32_t& r1, uint32_t& r2, uint32_t& r3, uint32_t addr) {
    asm volatile("ldmatrix.sync.aligned.m8n8.x4.trans.shared.b16 {%0,%1,%2,%3}, [%4];"
                 : "=r"(r0), "=r"(r1), "=r"(r2), "=r"(r3) : "r"(addr));
}

// ---------------- fused pre-pass: f32->f16 for x + 3 weights, plus strided z -> hcat[:,512:] -------
__global__ __launch_bounds__(256) void cvt_pre_kernel(
    const float2* __restrict__ x,
    const float2* __restrict__ ipw,
    const float2* __restrict__ mgw,
    const float2* __restrict__ kvbw,
    const float2* __restrict__ z)
{
    const int t = blockIdx.x * 256 + threadIdx.x;
    const int stride = gridDim.x * 256;
    __half2* xh   = (__half2*)g_xh;
    __half2* ipwh = (__half2*)g_ipwh;
    __half2* mgwh = (__half2*)g_mgwh;
    __half2* kvbwh= (__half2*)g_kvbwh;
    __half2* hc   = (__half2*)g_hcath;
    for (int i = t; i < BATCH * INDIM / 2; i += stride)  xh[i]   = __float22half2_rn(x[i]);
    for (int i = t; i < INDIM * LATENT / 2; i += stride) ipwh[i] = __float22half2_rn(ipw[i]);
    for (int i = t; i < 1024 * LATENT / 2; i += stride)  mgwh[i] = __float22half2_rn(mgw[i]);
    for (int i = t; i < LATENT * KVBN / 2; i += stride)  kvbwh[i]= __float22half2_rn(kvbw[i]);
    // z (B x 512 f32) -> hcat[:, 512:1024] fp16 (row stride 512 half2)
    for (int i = t; i < BATCH * 256; i += stride) {
        int b = i >> 8, c = i & 255;
        hc[(size_t)b * 512 + 256 + c] = __float22half2_rn(z[i]);
    }
}

// ---------------- fp16 tensor-core GEMM: C = A(MxK) * B(KxN) + bias ----------------
// BM=128, BN=64, BK=32, 128 threads (4 warps: 2 along M x 2 along N), warp tile 64x32.
// m16n8k16 f16 mma, f32 accumulate. 3-stage cp.async ring, ldmatrix fragment loads.
// (R7 config — best measured GEMM shape on this chip.)
#define HGBM 128
#define HGBN 64
#define HGBK 32
#define SAH  40
#define SBH  72
#define NST  3

template<bool NB, typename OutT>
__global__ __launch_bounds__(128, 4) void h_gemm(
    int M, int N, int K,
    const __half* __restrict__ A, int lda,
    const __half* __restrict__ B, int ldb,
    const float* __restrict__ bias,
    OutT* __restrict__ C, int ldc)
{
    __shared__ __half As[NST][HGBM][SAH];
    __shared__ __half Bs[NST][HGBK][SBH];

    const int tid  = threadIdx.x;
    const int wid  = tid >> 5;
    const int lane = tid & 31;
    const int grp  = lane >> 2;
    const int tig  = lane & 3;
    const int warp_m = (wid & 1) * 64;
    const int warp_n = (wid >> 1) * 32;
    const int block_row = blockIdx.y * HGBM;
    const int block_col = blockIdx.x * HGBN;

    float acc[4][4][4];
    #pragma unroll
    for (int a = 0; a < 4; a++)
        #pragma unroll
        for (int b = 0; b < 4; b++)
            #pragma unroll
            for (int c = 0; c < 4; c++) acc[a][b][c] = 0.f;

    const int KT = K / HGBK;

    auto load_stage = [&](int s, int kt) {
        const int k0 = kt * HGBK;
        #pragma unroll
        for (int i = 0; i < 4; i++) {
            int idx = tid + 128 * i;
            int r = idx >> 2;
            int j = (idx & 3) * 8;
            cp_async16(smem_u32(&As[s][r][j]),
                       A + (size_t)(block_row + r) * lda + k0 + j);
        }
        #pragma unroll
        for (int i = 0; i < 2; i++) {
            int idx = tid + 128 * i;
            int kk = idx >> 3;
            int c8 = (idx & 7) * 8;
            if (!NB || (block_col + c8) < N) {
                cp_async16(smem_u32(&Bs[s][kk][c8]),
                           B + (size_t)(k0 + kk) * ldb + block_col + c8);
            }
        }
    };

    load_stage(0, 0); cp_commit();
    load_stage(1, 1); cp_commit();

    const int a_row = warp_m + (lane & 15);
    const int a_k8  = (lane >> 4) << 3;
    const int b_r16 = (lane & 15);
    const int b_n8  = (lane >> 4) << 3;

    for (int kt = 0; kt < KT; kt++) {
        cp_wait1();
        __syncthreads();
        if (kt + 2 < KT) load_stage((kt + 2) % NST, kt + 2);
        cp_commit();

        const int s = kt % NST;
        #pragma unroll
        for (int ks = 0; ks < 2; ks++) {
            const int k0 = ks * 16;
            uint32_t a[4][4];
            #pragma unroll
            for (int mt = 0; mt < 4; mt++) {
                uint32_t addr = smem_u32(&As[s][a_row + mt * 16][k0 + a_k8]);
                ldsm_x4(a[mt][0], a[mt][1], a[mt][2], a[mt][3], addr);
            }
            uint32_t b[2][4];
            #pragma unroll
            for (int bt = 0; bt < 2; bt++) {
                uint32_t addr = smem_u32(&Bs[s][k0 + b_r16][warp_n + bt * 16 + b_n8]);
                ldsm_x4_t(b[bt][0], b[bt][1], b[bt][2], b[bt][3], addr);
            }
            #pragma unroll
            for (int mt = 0; mt < 4; mt++)
                #pragma unroll
                for (int nt = 0; nt < 4; nt++) {
                    const int bt = nt >> 1;
                    const int hp = (nt & 1) * 2;
                    asm volatile(
                        "mma.sync.aligned.m16n8k16.row.col.f32.f16.f16.f32 "
                        "{%0,%1,%2,%3}, {%4,%5,%6,%7}, {%8,%9}, {%0,%1,%2,%3};\n"
                        : "+f"(acc[mt][nt][0]), "+f"(acc[mt][nt][1]),
                          "+f"(acc[mt][nt][2]), "+f"(acc[mt][nt][3])
                        : "r"(a[mt][0]), "r"(a[mt][1]), "r"(a[mt][2]), "r"(a[mt][3]),
                          "r"(b[bt][hp]), "r"(b[bt][hp + 1]));
                }
        }
    }

    #pragma unroll
    for (int mt = 0; mt < 4; mt++) {
        int r0 = block_row + warp_m + mt * 16 + grp;
        #pragma unroll
        for (int nt = 0; nt < 4; nt++) {
            int c = block_col + warp_n + nt * 8 + tig * 2;
            if (!NB || c < N) {
                float b0 = bias[c], b1 = bias[c + 1];
                float o00 = acc[mt][nt][0] + b0, o01 = acc[mt][nt][1] + b1;
                float o10 = acc[mt][nt][2] + b0, o11 = acc[mt][nt][3] + b1;
                if (sizeof(OutT) == 4) {
                    *(float2*)((float*)C + (size_t)r0 * ldc + c)       = make_float2(o00, o01);
                    *(float2*)((float*)C + (size_t)(r0 + 8) * ldc + c) = make_float2(o10, o11);
                } else {
                    *(__half2*)((__half*)C + (size_t)r0 * ldc + c)       = __floats2half2_rn(o00, o01);
                    *(__half2*)((__half*)C + (size_t)(r0 + 8) * ldc + c) = __floats2half2_rn(o10, o11);
                }
            }
        }
    }
}

// ---------------- LayerNorm (512) in-place on g_hcath[:, :512] (fp16 storage, f32 math) ----------------
__global__ __launch_bounds__(256) void ln_kernel(
    const float* __restrict__ gamma,
    const float* __restrict__ beta)
{
    const int b = blockIdx.x;
    __half2* row = (__half2*)(g_hcath + (size_t)b * 1024);
    const int tid = threadIdx.x;

    float2 v = __half22float2(row[tid]);

    __shared__ float red[256];
    red[tid] = v.x + v.y;
    __syncthreads();
    #pragma unroll
    for (int s = 128; s > 0; s >>= 1) {
        if (tid < s) red[tid] += red[tid + s];
        __syncthreads();
    }
    const float mu = red[0] * (1.f / 512.f);
    __syncthreads();

    float d0 = v.x - mu, d1 = v.y - mu;
    red[tid] = d0 * d0 + d1 * d1;
    __syncthreads();
    #pragma unroll
    for (int s = 128; s > 0; s >>= 1) {
        if (tid < s) red[tid] += red[tid + s];
        __syncthreads();
    }
    const float var = red[0] * (1.f / 512.f);
    const float inv = rsqrtf(var + LN_EPS);

    float2 g  = *(const float2*)(gamma + 2 * tid);
    float2 be = *(const float2*)(beta + 2 * tid);
    row[tid] = __floats2half2_rn(d0 * inv * g.x + be.x, d1 * inv * g.y + be.y);
}

// ---------------- Oja update: one block per (b,h); W streamed once through registers --------
__global__ __launch_bounds__(256) void oja_final_kernel(
    const float* __restrict__ W,
    float* __restrict__ out)
{
    const int bh = blockIdx.x;              // b*H + h
    const int b  = bh >> 3;
    const int h  = bh & 7;

    const float4* __restrict__ W4 = (const float4*)(W   + (size_t)bh * (DHEAD * DHEAD));
    float4* __restrict__       O4 = (float4*)      (out + (size_t)bh * (DHEAD * DHEAD));
    const float* __restrict__ row = g_kvb + (size_t)b * KVBN + h * (2 * DHEAD + 1);

    __shared__ float  s_vs[DHEAD];
    __shared__ float  s_ks[DHEAD];
    __shared__ float  part[16][DHEAD];
    __shared__ float  red[DHEAD];
    __shared__ float  s_lr, s_max, s_sum;

    const int tid = threadIdx.x;
    if (tid < DHEAD) {
        s_ks[tid] = row[tid];
        s_vs[tid] = tanhf(row[DHEAD + tid]);
    }
    if (tid == 0) s_lr = 1.f / (1.f + expf(-row[2 * DHEAD]));
    __syncthreads();

    const int c4 = tid & 15;
    const int dg = tid >> 4;

    float4 wreg[4];
    float p0 = 0.f, p1 = 0.f, p2 = 0.f, p3 = 0.f;
    #pragma unroll
    for (int i = 0; i < 4; i++) {
        int d = dg + 16 * i;
        float4 w = __ldcs(&W4[d * 16 + c4]);
        wreg[i] = w;
        float v = s_vs[d];
        p0 = fmaf(w.x, v, p0);
        p1 = fmaf(w.y, v, p1);
        p2 = fmaf(w.z, v, p2);
        p3 = fmaf(w.w, v, p3);
    }
    part[dg][4 * c4 + 0] = p0;
    part[dg][4 * c4 + 1] = p1;
    part[dg][4 * c4 + 2] = p2;
    part[dg][4 * c4 + 3] = p3;
    __syncthreads();

    if (tid < DHEAD) {
        float rm = 0.f;
        #pragma unroll
        for (int g = 0; g < 16; g++) rm += part[g][tid];
        red[tid] = s_ks[tid] - rm;
    }
    __syncthreads();
    if (tid < 32) {
        float mx = fmaxf(red[tid], red[tid + 32]);
        #pragma unroll
        for (int o = 16; o > 0; o >>= 1) mx = fmaxf(mx, __shfl_xor_sync(0xffffffffu, mx, o));
        if (tid == 0) s_max = mx;
    }
    __syncthreads();
    if (tid < DHEAD) red[tid] = expf(red[tid] - s_max);
    __syncthreads();
    if (tid < 32) {
        float s = red[tid] + red[tid + 32];
        #pragma unroll
        for (int o = 16; o > 0; o >>= 1) s += __shfl_xor_sync(0xffffffffu, s, o);
        if (tid == 0) s_sum = s;
    }
    __syncthreads();
    if (tid < DHEAD) s_ks[tid] = red[tid] * (s_lr / s_sum);
    __syncthreads();

    const float k0 = s_ks[4 * c4 + 0];
    const float k1 = s_ks[4 * c4 + 1];
    const float k2 = s_ks[4 * c4 + 2];
    const float k3 = s_ks[4 * c4 + 3];
    #pragma unroll
    for (int i = 0; i < 4; i++) {
        int d = dg + 16 * i;
        float v = s_vs[d];
        float4 w = wreg[i];
        float4 o;
        o.x = fmaf(v, k0, w.x);
        o.y = fmaf(v, k1, w.y);
        o.z = fmaf(v, k2, w.z);
        o.w = fmaf(v, k3, w.w);
        __stcs(&O4[d * 16 + c4], o);
    }
}

// ---------------- launch: serial, single stream ----------------
extern "C" void kernel_launch(void* const* d_in, const int* in_sizes, int n_in,
                              void* d_out, int out_size)
{
    const float* x     = (const float*)d_in[0];
    const float* z     = (const float*)d_in[1];
    const float* W     = (const float*)d_in[2];
    const float* ip_w  = (const float*)d_in[3];
    const float* ip_b  = (const float*)d_in[4];
    const float* ln_g  = (const float*)d_in[5];
    const float* ln_b  = (const float*)d_in[6];
    const float* mg_w  = (const float*)d_in[7];
    const float* mg_b  = (const float*)d_in[8];
    const float* kvb_w = (const float*)d_in[9];
    const float* kvb_b = (const float*)d_in[10];
    float* out = (float*)d_out;

    void *p_xh, *p_ipwh, *p_mgwh, *p_kvbwh, *p_hcath, *p_h2h, *p_kvb;
    cudaGetSymbolAddress(&p_xh,    g_xh);
    cudaGetSymbolAddress(&p_ipwh,  g_ipwh);
    cudaGetSymbolAddress(&p_mgwh,  g_mgwh);
    cudaGetSymbolAddress(&p_kvbwh, g_kvbwh);
    cudaGetSymbolAddress(&p_hcath, g_hcath);
    cudaGetSymbolAddress(&p_h2h,   g_h2h);
    cudaGetSymbolAddress(&p_kvb,   g_kvb);

    // 0) fused pre-pass: f32->f16 conversions + z into hcat[:, 512:]
    cvt_pre_kernel<<<1184, 256>>>(
        (const float2*)x, (const float2*)ip_w, (const float2*)mg_w,
        (const float2*)kvb_w, (const float2*)z);

    // 1) hcat[:, :512] = xh @ ipwh + ip_b  (fp16 out, ldc=1024)
    {
        dim3 grid(LATENT / HGBN, BATCH / HGBM);   // (8, 32) = 256 blocks
        h_gemm<false, __half><<<grid, 128>>>(BATCH, LATENT, INDIM,
            (const __half*)p_xh, INDIM, (const __half*)p_ipwh, LATENT, ip_b,
            (__half*)p_hcath, 1024);
    }
    // 2) LayerNorm in place on hcat[:, :512] (fp16)
    ln_kernel<<<BATCH, 256>>>(ln_g, ln_b);
    // 3) h2h = hcat @ mgwh + mg_b  (fp16 out)
    {
        dim3 grid(LATENT / HGBN, BATCH / HGBM);   // 256 blocks
        h_gemm<false, __half><<<grid, 128>>>(BATCH, LATENT, 1024,
            (const __half*)p_hcath, 1024, (const __half*)p_mgwh, LATENT, mg_b,
            (__half*)p_h2h, LATENT);
    }
    // 4) kvb = h2h @ kvbwh + kvb_b  (fp32 out, N=1032 bounds)
    {
        dim3 grid((KVBN + HGBN - 1) / HGBN, BATCH / HGBM);  // (17, 32) = 544 blocks
        h_gemm<true, float><<<grid, 128>>>(BATCH, KVBN, LATENT,
            (const __half*)p_h2h, LATENT, (const __half*)p_kvbwh, KVBN, kvb_b,
            (float*)p_kvb, KVBN);
    }
    // 5) Oja update fused
    oja_final_kernel<<<BATCH * NHEAD, 256>>>(W, out);
}

// round 14
// speedup vs baseline: 1.3164x; 1.0029x over previous
#include <cuda_runtime.h>
#include <cuda_fp16.h>
#include <math.h>
#include <stdint.h>

// Problem constants
#define BATCH   4096
#define INDIM   512
#define LATENT  512
#define NHEAD   8
#define DHEAD   64
#define KVBN    1032            // H*(2D+1) = 8*129
#define KVBNP   1088            // padded to 17*64 for exact N-tiling
#define LN_EPS  1e-5f

// ---------------- scratch (device globals; no runtime alloc allowed) ----------------
__device__ __half g_xh   [BATCH * INDIM];
__device__ __half g_ipwh [INDIM * LATENT];
__device__ __half g_mgwh [1024 * LATENT];
__device__ __half g_kvbwh[LATENT * KVBNP];   // zero-padded cols 1032..1087
__device__ float  g_kvbb [KVBNP];            // padded bias
__device__ __half g_hcath[BATCH * 1024];     // [LN(h) | z] fp16; GEMM1 writes cols 0..511
__device__ __half g_h2h  [BATCH * LATENT];   // GEMM2 out fp16
__device__ __half g_kvbh [BATCH * KVBNP];    // GEMM3 out fp16 (row stride 1088)

__device__ __forceinline__ uint32_t smem_u32(const void* p) {
    return (uint32_t)__cvta_generic_to_shared(p);
}
__device__ __forceinline__ void cp_async16(uint32_t dst, const void* src) {
    asm volatile("cp.async.cg.shared.global [%0], [%1], 16;\n" :: "r"(dst), "l"(src));
}
__device__ __forceinline__ void cp_commit() { asm volatile("cp.async.commit_group;\n"); }
__device__ __forceinline__ void cp_wait1()  { asm volatile("cp.async.wait_group 1;\n"); }

__device__ __forceinline__ void ldsm_x4(uint32_t& r0, uint32_t& r1, uint32_t& r2, uint32_t& r3, uint32_t addr) {
    asm volatile("ldmatrix.sync.aligned.m8n8.x4.shared.b16 {%0,%1,%2,%3}, [%4];"
                 : "=r"(r0), "=r"(r1), "=r"(r2), "=r"(r3) : "r"(addr));
}
__device__ __forceinline__ void ldsm_x4_t(uint32_t& r0, uint32_t& r1, uint32_t& r2, uint32_t& r3, uint32_t addr) {
    asm volatile("ldmatrix.sync.aligned.m8n8.x4.trans.shared.b16 {%0,%1,%2,%3}, [%4];"
                 : "=r"(r0), "=r"(r1), "=r"(r2), "=r"(r3) : "r"(addr));
}

// ---------------- fused pre-pass: f32->f16 conversions (+padding) + z -> hcat[:,512:] -------
__global__ __launch_bounds__(256) void cvt_pre_kernel(
    const float2* __restrict__ x,
    const float2* __restrict__ ipw,
    const float2* __restrict__ mgw,
    const float2* __restrict__ kvbw,
    const float*  __restrict__ kvbb,
    const float2* __restrict__ z)
{
    const int t = blockIdx.x * 256 + threadIdx.x;
    const int stride = gridDim.x * 256;
    __half2* xh   = (__half2*)g_xh;
    __half2* ipwh = (__half2*)g_ipwh;
    __half2* mgwh = (__half2*)g_mgwh;
    __half2* kvbwh= (__half2*)g_kvbwh;
    __half2* hc   = (__half2*)g_hcath;
    for (int i = t; i < BATCH * INDIM / 2; i += stride)  xh[i]   = __float22half2_rn(x[i]);
    for (int i = t; i < INDIM * LATENT / 2; i += stride) ipwh[i] = __float22half2_rn(ipw[i]);
    for (int i = t; i < 1024 * LATENT / 2; i += stride)  mgwh[i] = __float22half2_rn(mgw[i]);
    // kvb_w: [512][1032] f32 -> [512][1088] f16, zero pad cols >= 1032 (1032 even: pairs don't straddle)
    for (int i = t; i < LATENT * (KVBNP / 2); i += stride) {
        int k = i / (KVBNP / 2), c2 = i % (KVBNP / 2);
        __half2 v;
        if (2 * c2 < KVBN) v = __float22half2_rn(kvbw[(size_t)k * (KVBN / 2) + c2]);
        else               v = __floats2half2_rn(0.f, 0.f);
        kvbwh[i] = v;
    }
    for (int i = t; i < KVBNP; i += stride)
        g_kvbb[i] = (i < KVBN) ? kvbb[i] : 0.f;
    // z (B x 512 f32) -> hcat[:, 512:1024] fp16 (row stride 512 half2)
    for (int i = t; i < BATCH * 256; i += stride) {
        int b = i >> 8, c = i & 255;
        hc[(size_t)b * 512 + 256 + c] = __float22half2_rn(z[i]);
    }
}

// ---------------- fp16 tensor-core GEMM: C = A(MxK) * B(KxN) + bias ----------------
// BM=128, BN=64, BK=32, 128 threads (4 warps: 2 along M x 2 along N), warp tile 64x32.
// m16n8k16 f16 mma, f32 accumulate. 3-stage cp.async ring, ldmatrix fragment loads.
#define HGBM 128
#define HGBN 64
#define HGBK 32
#define SAH  40
#define SBH  72
#define NST  3

template<typename OutT>
__global__ __launch_bounds__(128, 4) void h_gemm(
    int M, int N, int K,
    const __half* __restrict__ A, int lda,
    const __half* __restrict__ B, int ldb,
    const float* __restrict__ bias,
    OutT* __restrict__ C, int ldc)
{
    __shared__ __half As[NST][HGBM][SAH];
    __shared__ __half Bs[NST][HGBK][SBH];

    const int tid  = threadIdx.x;
    const int wid  = tid >> 5;
    const int lane = tid & 31;
    const int grp  = lane >> 2;
    const int tig  = lane & 3;
    const int warp_m = (wid & 1) * 64;
    const int warp_n = (wid >> 1) * 32;
    const int block_row = blockIdx.y * HGBM;
    const int block_col = blockIdx.x * HGBN;

    float acc[4][4][4];
    #pragma unroll
    for (int a = 0; a < 4; a++)
        #pragma unroll
        for (int b = 0; b < 4; b++)
            #pragma unroll
            for (int c = 0; c < 4; c++) acc[a][b][c] = 0.f;

    const int KT = K / HGBK;

    auto load_stage = [&](int s, int kt) {
        const int k0 = kt * HGBK;
        #pragma unroll
        for (int i = 0; i < 4; i++) {
            int idx = tid + 128 * i;
            int r = idx >> 2;
            int j = (idx & 3) * 8;
            cp_async16(smem_u32(&As[s][r][j]),
                       A + (size_t)(block_row + r) * lda + k0 + j);
        }
        #pragma unroll
        for (int i = 0; i < 2; i++) {
            int idx = tid + 128 * i;
            int kk = idx >> 3;
            int c8 = (idx & 7) * 8;
            cp_async16(smem_u32(&Bs[s][kk][c8]),
                       B + (size_t)(k0 + kk) * ldb + block_col + c8);
        }
    };

    load_stage(0, 0); cp_commit();
    load_stage(1, 1); cp_commit();

    const int a_row = warp_m + (lane & 15);
    const int a_k8  = (lane >> 4) << 3;
    const int b_r16 = (lane & 15);
    const int b_n8  = (lane >> 4) << 3;

    for (int kt = 0; kt < KT; kt++) {
        cp_wait1();
        __syncthreads();
        if (kt + 2 < KT) load_stage((kt + 2) % NST, kt + 2);
        cp_commit();

        const int s = kt % NST;
        #pragma unroll
        for (int ks = 0; ks < 2; ks++) {
            const int k0 = ks * 16;
            uint32_t a[4][4];
            #pragma unroll
            for (int mt = 0; mt < 4; mt++) {
                uint32_t addr = smem_u32(&As[s][a_row + mt * 16][k0 + a_k8]);
                ldsm_x4(a[mt][0], a[mt][1], a[mt][2], a[mt][3], addr);
            }
            uint32_t b[2][4];
            #pragma unroll
            for (int bt = 0; bt < 2; bt++) {
                uint32_t addr = smem_u32(&Bs[s][k0 + b_r16][warp_n + bt * 16 + b_n8]);
                ldsm_x4_t(b[bt][0], b[bt][1], b[bt][2], b[bt][3], addr);
            }
            #pragma unroll
            for (int mt = 0; mt < 4; mt++)
                #pragma unroll
                for (int nt = 0; nt < 4; nt++) {
                    const int bt = nt >> 1;
                    const int hp = (nt & 1) * 2;
                    asm volatile(
                        "mma.sync.aligned.m16n8k16.row.col.f32.f16.f16.f32 "
                        "{%0,%1,%2,%3}, {%4,%5,%6,%7}, {%8,%9}, {%0,%1,%2,%3};\n"
                        : "+f"(acc[mt][nt][0]), "+f"(acc[mt][nt][1]),
                          "+f"(acc[mt][nt][2]), "+f"(acc[mt][nt][3])
                        : "r"(a[mt][0]), "r"(a[mt][1]), "r"(a[mt][2]), "r"(a[mt][3]),
                          "r"(b[bt][hp]), "r"(b[bt][hp + 1]));
                }
        }
    }

    #pragma unroll
    for (int mt = 0; mt < 4; mt++) {
        int r0 = block_row + warp_m + mt * 16 + grp;
        #pragma unroll
        for (int nt = 0; nt < 4; nt++) {
            int c = block_col + warp_n + nt * 8 + tig * 2;
            float b0 = bias[c], b1 = bias[c + 1];
            float o00 = acc[mt][nt][0] + b0, o01 = acc[mt][nt][1] + b1;
            float o10 = acc[mt][nt][2] + b0, o11 = acc[mt][nt][3] + b1;
            if (sizeof(OutT) == 4) {
                *(float2*)((float*)C + (size_t)r0 * ldc + c)       = make_float2(o00, o01);
                *(float2*)((float*)C + (size_t)(r0 + 8) * ldc + c) = make_float2(o10, o11);
            } else {
                *(__half2*)((__half*)C + (size_t)r0 * ldc + c)       = __floats2half2_rn(o00, o01);
                *(__half2*)((__half*)C + (size_t)(r0 + 8) * ldc + c) = __floats2half2_rn(o10, o11);
            }
        }
    }
}

// ---------------- LayerNorm (512) in-place on g_hcath[:, :512] (fp16 storage, f32 math) ----------------
__global__ __launch_bounds__(256) void ln_kernel(
    const float* __restrict__ gamma,
    const float* __restrict__ beta)
{
    const int b = blockIdx.x;
    __half2* row = (__half2*)(g_hcath + (size_t)b * 1024);
    const int tid = threadIdx.x;

    float2 v = __half22float2(row[tid]);

    __shared__ float red[256];
    red[tid] = v.x + v.y;
    __syncthreads();
    #pragma unroll
    for (int s = 128; s > 0; s >>= 1) {
        if (tid < s) red[tid] += red[tid + s];
        __syncthreads();
    }
    const float mu = red[0] * (1.f / 512.f);
    __syncthreads();

    float d0 = v.x - mu, d1 = v.y - mu;
    red[tid] = d0 * d0 + d1 * d1;
    __syncthreads();
    #pragma unroll
    for (int s = 128; s > 0; s >>= 1) {
        if (tid < s) red[tid] += red[tid + s];
        __syncthreads();
    }
    const float var = red[0] * (1.f / 512.f);
    const float inv = rsqrtf(var + LN_EPS);

    float2 g  = *(const float2*)(gamma + 2 * tid);
    float2 be = *(const float2*)(beta + 2 * tid);
    row[tid] = __floats2half2_rn(d0 * inv * g.x + be.x, d1 * inv * g.y + be.y);
}

// ---------------- Oja update: one block per (b,h); W streamed once through registers --------
__global__ __launch_bounds__(256) void oja_final_kernel(
    const float* __restrict__ W,
    float* __restrict__ out)
{
    const int bh = blockIdx.x;              // b*H + h
    const int b  = bh >> 3;
    const int h  = bh & 7;

    const float4* __restrict__ W4 = (const float4*)(W   + (size_t)bh * (DHEAD * DHEAD));
    float4* __restrict__       O4 = (float4*)      (out + (size_t)bh * (DHEAD * DHEAD));
    const __half* __restrict__ row = g_kvbh + (size_t)b * KVBNP + h * (2 * DHEAD + 1);

    __shared__ float  s_vs[DHEAD];
    __shared__ float  s_ks[DHEAD];
    __shared__ float  part[16][DHEAD];
    __shared__ float  red[DHEAD];
    __shared__ float  s_lr, s_max, s_sum;

    const int tid = threadIdx.x;
    if (tid < DHEAD) {
        s_ks[tid] = __half2float(row[tid]);
        s_vs[tid] = tanhf(__half2float(row[DHEAD + tid]));
    }
    if (tid == 0) s_lr = 1.f / (1.f + expf(-__half2float(row[2 * DHEAD])));
    __syncthreads();

    const int c4 = tid & 15;
    const int dg = tid >> 4;

    float4 wreg[4];
    float p0 = 0.f, p1 = 0.f, p2 = 0.f, p3 = 0.f;
    #pragma unroll
    for (int i = 0; i < 4; i++) {
        int d = dg + 16 * i;
        float4 w = __ldcs(&W4[d * 16 + c4]);
        wreg[i] = w;
        float v = s_vs[d];
        p0 = fmaf(w.x, v, p0);
        p1 = fmaf(w.y, v, p1);
        p2 = fmaf(w.z, v, p2);
        p3 = fmaf(w.w, v, p3);
    }
    part[dg][4 * c4 + 0] = p0;
    part[dg][4 * c4 + 1] = p1;
    part[dg][4 * c4 + 2] = p2;
    part[dg][4 * c4 + 3] = p3;
    __syncthreads();

    if (tid < DHEAD) {
        float rm = 0.f;
        #pragma unroll
        for (int g = 0; g < 16; g++) rm += part[g][tid];
        red[tid] = s_ks[tid] - rm;
    }
    __syncthreads();
    if (tid < 32) {
        float mx = fmaxf(red[tid], red[tid + 32]);
        #pragma unroll
        for (int o = 16; o > 0; o >>= 1) mx = fmaxf(mx, __shfl_xor_sync(0xffffffffu, mx, o));
        if (tid == 0) s_max = mx;
    }
    __syncthreads();
    if (tid < DHEAD) red[tid] = expf(red[tid] - s_max);
    __syncthreads();
    if (tid < 32) {
        float s = red[tid] + red[tid + 32];
        #pragma unroll
        for (int o = 16; o > 0; o >>= 1) s += __shfl_xor_sync(0xffffffffu, s, o);
        if (tid == 0) s_sum = s;
    }
    __syncthreads();
    if (tid < DHEAD) s_ks[tid] = red[tid] * (s_lr / s_sum);
    __syncthreads();

    const float k0 = s_ks[4 * c4 + 0];
    const float k1 = s_ks[4 * c4 + 1];
    const float k2 = s_ks[4 * c4 + 2];
    const float k3 = s_ks[4 * c4 + 3];
    #pragma unroll
    for (int i = 0; i < 4; i++) {
        int d = dg + 16 * i;
        float v = s_vs[d];
        float4 w = wreg[i];
        float4 o;
        o.x = fmaf(v, k0, w.x);
        o.y = fmaf(v, k1, w.y);
        o.z = fmaf(v, k2, w.z);
        o.w = fmaf(v, k3, w.w);
        __stcs(&O4[d * 16 + c4], o);
    }
}

// ---------------- launch: serial, single stream ----------------
extern "C" void kernel_launch(void* const* d_in, const int* in_sizes, int n_in,
                              void* d_out, int out_size)
{
    const float* x     = (const float*)d_in[0];
    const float* z     = (const float*)d_in[1];
    const float* W     = (const float*)d_in[2];
    const float* ip_w  = (const float*)d_in[3];
    const float* ip_b  = (const float*)d_in[4];
    const float* ln_g  = (const float*)d_in[5];
    const float* ln_b  = (const float*)d_in[6];
    const float* mg_w  = (const float*)d_in[7];
    const float* mg_b  = (const float*)d_in[8];
    const float* kvb_w = (const float*)d_in[9];
    const float* kvb_b = (const float*)d_in[10];
    float* out = (float*)d_out;

    void *p_xh, *p_ipwh, *p_mgwh, *p_kvbwh, *p_kvbb, *p_hcath, *p_h2h, *p_kvbh;
    cudaGetSymbolAddress(&p_xh,    g_xh);
    cudaGetSymbolAddress(&p_ipwh,  g_ipwh);
    cudaGetSymbolAddress(&p_mgwh,  g_mgwh);
    cudaGetSymbolAddress(&p_kvbwh, g_kvbwh);
    cudaGetSymbolAddress(&p_kvbb,  g_kvbb);
    cudaGetSymbolAddress(&p_hcath, g_hcath);
    cudaGetSymbolAddress(&p_h2h,   g_h2h);
    cudaGetSymbolAddress(&p_kvbh,  g_kvbh);

    // 0) fused pre-pass: conversions (+kvb padding) + z into hcat[:, 512:]
    cvt_pre_kernel<<<1184, 256>>>(
        (const float2*)x, (const float2*)ip_w, (const float2*)mg_w,
        (const float2*)kvb_w, kvb_b, (const float2*)z);

    // 1) hcat[:, :512] = xh @ ipwh + ip_b  (fp16 out, ldc=1024)
    {
        dim3 grid(LATENT / HGBN, BATCH / HGBM);   // (8, 32) = 256 blocks
        h_gemm<__half><<<grid, 128>>>(BATCH, LATENT, INDIM,
            (const __half*)p_xh, INDIM, (const __half*)p_ipwh, LATENT, ip_b,
            (__half*)p_hcath, 1024);
    }
    // 2) LayerNorm in place on hcat[:, :512] (fp16)
    ln_kernel<<<BATCH, 256>>>(ln_g, ln_b);
    // 3) h2h = hcat @ mgwh + mg_b  (fp16 out)
    {
        dim3 grid(LATENT / HGBN, BATCH / HGBM);   // 256 blocks
        h_gemm<__half><<<grid, 128>>>(BATCH, LATENT, 1024,
            (const __half*)p_hcath, 1024, (const __half*)p_mgwh, LATENT, mg_b,
            (__half*)p_h2h, LATENT);
    }
    // 4) kvbh = h2h @ kvbwh + kvbb  (fp16 out, padded N=1088, no bounds checks)
    {
        dim3 grid(KVBNP / HGBN, BATCH / HGBM);    // (17, 32) = 544 blocks
        h_gemm<__half><<<grid, 128>>>(BATCH, KVBNP, LATENT,
            (const __half*)p_h2h, LATENT, (const __half*)p_kvbwh, KVBNP,
            (const float*)p_kvbb, (__half*)p_kvbh, KVBNP);
    }
    // 5) Oja update fused
    oja_final_kernel<<<BATCH * NHEAD, 256>>>(W, out);
}